// round 8
// baseline (speedup 1.0000x reference)
#include <cuda_runtime.h>
#include <cuda.h>
#include <cuda_bf16.h>
#include <mma.h>
#include <cstdint>

#define SEQ   16384
#define DIM   1280
#define NH    16
#define HD    80
#define WIN   64
#define NWIN  (SEQ / WIN)
#define HDP   84
#define SCP   65

// tcgen05 cg2 GEMM tiling: cluster of 2 CTAs (along x) computes 256x256 C tile
#define TM    128          // M rows per CTA (cluster M = 256)
#define TN    256          // N tile (each CTA holds N/2=128 B rows)
#define TKB   128          // K-chunk bytes per row (64 bf16) = SW128 row
#define TKE   64           // K-chunk elements
#define NSTG  (DIM / TKE)  // 20 k-stages
#define NBUF  3

// smem layout (dynamic)
#define SM_TMEM   0
#define SM_FULL   8        // full[0..2] at 8,16,24 (leader only)
#define SM_DONE   32       // done[0..2] at 32,40,48
#define SM_BUF    1024
#define AB_QTR    16384                      // 128 rows x 128B (one operand slice)
#define STAGE_BYTES (4 * AB_QTR)             // 64 KB per CTA per stage
#define SMEM_GEMM (SM_BUF + NBUF * STAGE_BYTES) // 197,632 B
#define STAGE_TX  (2 * STAGE_BYTES)          // both CTAs' tx land on leader barrier

// Arch-specific tcgen05 (TMEM ld/st) only exists on sm_10xa targets.
#if defined(__CUDA_ARCH__) && (defined(__CUDA_ARCH_FEAT_SM103_ALL) || defined(__CUDA_ARCH_FEAT_SM100_ALL))
#define TC_PATH 1
#else
#define TC_PATH 0
#endif

// ---------------------------------------------------------------------------
// Scratch
// ---------------------------------------------------------------------------
__device__ float g_q[SEQ * DIM];
__device__ float g_k[SEQ * DIM];
__device__ float g_v[SEQ * DIM];
__device__ __nv_bfloat16 g_ahi[SEQ * DIM];
__device__ __nv_bfloat16 g_alo[SEQ * DIM];
__device__ __nv_bfloat16 g_whi[3 * DIM * DIM];   // Wq|Wk|Wv stacked (Wp reuses rows 0..1279)
__device__ __nv_bfloat16 g_wlo[3 * DIM * DIM];

#if TC_PATH
// ---------------------------------------------------------------------------
// PTX helpers (sm_103a only)
// ---------------------------------------------------------------------------
__device__ __forceinline__ uint32_t smem_u32(const void* p) {
    uint32_t a;
    asm("{ .reg .u64 t; cvta.to.shared.u64 t, %1; cvt.u32.u64 %0, t; }"
        : "=r"(a) : "l"(p));
    return a;
}

__device__ __forceinline__ uint32_t ctarank() {
    uint32_t r;
    asm("mov.u32 %0, %%cluster_ctarank;" : "=r"(r));
    return r;
}

#define MBAR_INIT(addr, cnt) \
    asm volatile("mbarrier.init.shared.b64 [%0], %1;" :: "r"(addr), "r"(cnt) : "memory")

#define MBAR_EXPECT_TX(addr, tx) \
    asm volatile("mbarrier.arrive.expect_tx.shared.b64 _, [%0], %1;" :: "r"(addr), "r"(tx) : "memory")

__device__ __forceinline__ void mbar_wait(uint32_t mbar, uint32_t phase) {
    asm volatile(
        "{\n\t.reg .pred P;\n\t"
        "WL_%=:\n\t"
        "mbarrier.try_wait.parity.acquire.cta.shared::cta.b64 P, [%0], %1, 0x989680;\n\t"
        "@P bra WD_%=;\n\t"
        "bra WL_%=;\n\t"
        "WD_%=:\n\t}"
        :: "r"(mbar), "r"(phase) : "memory");
}

#define CLUSTER_SYNC() do { \
    asm volatile("barrier.cluster.arrive.aligned;" ::: "memory"); \
    asm volatile("barrier.cluster.wait.aligned;" ::: "memory"); \
} while (0)

// 2D TMA cg2 load: both CTAs execute; complete_tx lands on LEADER's barrier
// (bit 24 of the barrier address cleared = rank-0 CTA in the pair).
__device__ __forceinline__ void tma2d_cg2(uint32_t saddr, const void* tmap, int x, int y,
                                          uint32_t mbar) {
    asm volatile(
        "{\n\t.reg .b32 lb;\n\tand.b32 lb, %4, 0xFEFFFFFF;\n\t"
        "cp.async.bulk.tensor.2d.cta_group::2.shared::cluster.global.tile"
        ".mbarrier::complete_tx::bytes [%0], [%1, {%2, %3}], [lb];\n\t}"
        :: "r"(saddr), "l"(tmap), "r"(x), "r"(y), "r"(mbar) : "memory");
}

// SW128 K-major smem descriptor: layout=2, version=1, SBO=64, LBO=1
__device__ __forceinline__ uint64_t mk_desc(uint32_t addr) {
    return ((uint64_t)2 << 61) | ((uint64_t)1 << 46) | ((uint64_t)64 << 32) |
           ((uint64_t)1 << 16) | (uint64_t)((addr >> 4) & 0x3FFF);
}

// cg2 bf16 SS MMA: D[256,256] fp32 += A[256,16] * B[256,16]^T (pair-wide)
__device__ __forceinline__ void mma_bf16_ss_cg2(uint32_t d, uint64_t ad, uint64_t bd,
                                                uint32_t idesc, uint32_t en) {
    asm volatile(
        "{\n\t.reg .pred p;\n\tsetp.ne.u32 p, %5, 0;\n\t"
        "tcgen05.mma.cta_group::2.kind::f16 [%0], %1, %2, %3, "
        "{%4, %4, %4, %4, %4, %4, %4, %4}, p;\n\t}"
        :: "r"(d), "l"(ad), "l"(bd), "r"(idesc), "r"(0u), "r"(en) : "memory");
}

// cg2 commit, arriving at the same mbarrier offset in BOTH cluster CTAs
#define TC_COMMIT_MC2(mbar, mask) \
    asm volatile("tcgen05.commit.cta_group::2.mbarrier::arrive::one.shared::cluster" \
                 ".multicast::cluster.b64 [%0], %1;" :: "r"(mbar), "h"((uint16_t)(mask)) : "memory")
#define TC_ALLOC2(slot, n) \
    asm volatile("tcgen05.alloc.cta_group::2.sync.aligned.shared::cta.b32 [%0], %1;" \
                 :: "r"(slot), "r"(n) : "memory")
#define TC_RELINQ2() \
    asm volatile("tcgen05.relinquish_alloc_permit.cta_group::2.sync.aligned;")
#define TC_DEALLOC2(t, n) \
    asm volatile("tcgen05.dealloc.cta_group::2.sync.aligned.b32 %0, %1;" :: "r"(t), "r"(n))
#define TC_FENCE_AFTER()  asm volatile("tcgen05.fence::after_thread_sync;" ::: "memory")
#define TC_FENCE_BEFORE() asm volatile("tcgen05.fence::before_thread_sync;" ::: "memory")
#define TC_WAIT_LD() asm volatile("tcgen05.wait::ld.sync.aligned;" ::: "memory")

#define LDTM_X32(r, addr) \
    asm volatile("tcgen05.ld.sync.aligned.32x32b.x32.b32 " \
        "{%0,%1,%2,%3,%4,%5,%6,%7,%8,%9,%10,%11,%12,%13,%14,%15," \
        "%16,%17,%18,%19,%20,%21,%22,%23,%24,%25,%26,%27,%28,%29,%30,%31}, [%32];" \
        : "=r"((r)[0]),"=r"((r)[1]),"=r"((r)[2]),"=r"((r)[3]), \
          "=r"((r)[4]),"=r"((r)[5]),"=r"((r)[6]),"=r"((r)[7]), \
          "=r"((r)[8]),"=r"((r)[9]),"=r"((r)[10]),"=r"((r)[11]), \
          "=r"((r)[12]),"=r"((r)[13]),"=r"((r)[14]),"=r"((r)[15]), \
          "=r"((r)[16]),"=r"((r)[17]),"=r"((r)[18]),"=r"((r)[19]), \
          "=r"((r)[20]),"=r"((r)[21]),"=r"((r)[22]),"=r"((r)[23]), \
          "=r"((r)[24]),"=r"((r)[25]),"=r"((r)[26]),"=r"((r)[27]), \
          "=r"((r)[28]),"=r"((r)[29]),"=r"((r)[30]),"=r"((r)[31]) \
        : "r"(addr))

// idesc: fp32 accum, bf16 a/b, N=256, M=256 (cg2 pair-wide)
#define IDESC2 ((1u << 4) | (1u << 7) | (1u << 10) | ((TN / 8) << 17) | (16u << 24))
#endif  // TC_PATH

// ---------------------------------------------------------------------------
// fp32 -> bf16 hi + residual lo
// ---------------------------------------------------------------------------
__global__ void split_kernel(const float* __restrict__ src,
                             __nv_bfloat16* __restrict__ hi,
                             __nv_bfloat16* __restrict__ lo, int n4)
{
    int i = blockIdx.x * blockDim.x + threadIdx.x;
    if (i >= n4) return;
    float4 v = ((const float4*)src)[i];
    __nv_bfloat16 h0 = __float2bfloat16(v.x);
    __nv_bfloat16 h1 = __float2bfloat16(v.y);
    __nv_bfloat16 h2 = __float2bfloat16(v.z);
    __nv_bfloat16 h3 = __float2bfloat16(v.w);
    __nv_bfloat16 l0 = __float2bfloat16(v.x - __bfloat162float(h0));
    __nv_bfloat16 l1 = __float2bfloat16(v.y - __bfloat162float(h1));
    __nv_bfloat16 l2 = __float2bfloat16(v.z - __bfloat162float(h2));
    __nv_bfloat16 l3 = __float2bfloat16(v.w - __bfloat162float(h3));
    __nv_bfloat162* hp = (__nv_bfloat162*)hi;
    __nv_bfloat162* lp = (__nv_bfloat162*)lo;
    hp[2 * i]     = __nv_bfloat162(h0, h1);
    hp[2 * i + 1] = __nv_bfloat162(h2, h3);
    lp[2 * i]     = __nv_bfloat162(l0, l1);
    lp[2 * i + 1] = __nv_bfloat162(l2, l3);
}

// ---------------------------------------------------------------------------
// tcgen05 cg2 bf16x3 GEMM. Cluster (2,1,1): pair along x computes C[256 x 256].
// Each CTA TMA-loads its 128 A rows + its distinct 128 B rows (N-split).
// 3-stage pipeline, 64KB/stage/CTA. fused=1: N spans Wq|Wk|Wv (blockIdx.y).
// ---------------------------------------------------------------------------
__global__ __launch_bounds__(256, 1) __cluster_dims__(2, 1, 1)
void gemm_tc(const __grid_constant__ CUtensorMap tmAh,
             const __grid_constant__ CUtensorMap tmAl,
             const __grid_constant__ CUtensorMap tmBh,
             const __grid_constant__ CUtensorMap tmBl,
             const __nv_bfloat16* __restrict__ Ah,
             const __nv_bfloat16* __restrict__ Al,
             const __nv_bfloat16* __restrict__ Bh,
             const __nv_bfloat16* __restrict__ Bl,
             float* cq, float* ck, float* cv, int fused)
{
    extern __shared__ char smc[];
    const int tid = threadIdx.x;
    const int wid = tid >> 5;
    const int bm = blockIdx.x * TM;       // this CTA's own 128 M rows (pairs along x)
    const int bn = blockIdx.y * TN;

    float* C;
    int lcol;
    if (fused) {
        int mtx = blockIdx.y / 5;
        C = (mtx == 0) ? cq : (mtx == 1) ? ck : cv;
        lcol = (blockIdx.y % 5) * TN;
    } else {
        C = cq;
        lcol = bn;
    }

#if TC_PATH
    const int lane = tid & 31;
    const uint32_t sbase = smem_u32(smc);
    const uint32_t rank = ctarank();

    if (tid == 0) {
#pragma unroll
        for (int s = 0; s < NBUF; s++) {
            MBAR_INIT(sbase + SM_FULL + 8 * s, 1);   // leader expect_tx is sole arrival
            MBAR_INIT(sbase + SM_DONE + 8 * s, 1);   // one cg2 commit arrival
        }
    }
    if (wid == 0) {
        TC_ALLOC2(sbase + SM_TMEM, 256);
        TC_RELINQ2();
    }
    __syncthreads();
    CLUSTER_SYNC();   // mbarriers + alloc visible pair-wide before cg2 TMA

    uint32_t tmem;
    asm volatile("ld.shared.b32 %0, [%1];" : "=r"(tmem) : "r"(sbase + SM_TMEM));

    if (tid == 0) {
        const int brow = bn + (int)rank * 128;   // this CTA's distinct B half

        auto issue = [&](int i, int b) {
            const uint32_t buf = sbase + SM_BUF + b * STAGE_BYTES;
            const uint32_t fullb = sbase + SM_FULL + 8 * b;
            const int x = i * TKE;
            if (rank == 0) MBAR_EXPECT_TX(fullb, STAGE_TX);
            tma2d_cg2(buf,              &tmAh, x, bm,   fullb);
            tma2d_cg2(buf + AB_QTR,     &tmAl, x, bm,   fullb);
            tma2d_cg2(buf + 2 * AB_QTR, &tmBh, x, brow, fullb);
            tma2d_cg2(buf + 3 * AB_QTR, &tmBl, x, brow, fullb);
        };

        int pfull[NBUF] = {0, 0, 0}, pdone[NBUF] = {0, 0, 0};
        issue(0, 0);
        issue(1, 1);
        issue(2, 2);

        for (int i = 0; i < NSTG; i++) {
            const int b = i % NBUF;

            if (rank == 0) {
                mbar_wait(sbase + SM_FULL + 8 * b, pfull[b]);
                pfull[b] ^= 1;

                const uint32_t bufb = sbase + SM_BUF + b * STAGE_BYTES;
                uint64_t adh = mk_desc(bufb);
                uint64_t adl = mk_desc(bufb + AB_QTR);
                uint64_t bdh = mk_desc(bufb + 2 * AB_QTR);
                uint64_t bdl = mk_desc(bufb + 3 * AB_QTR);
#pragma unroll
                for (int ks = 0; ks < 4; ks++) {
                    mma_bf16_ss_cg2(tmem, adh + 2 * ks, bdh + 2 * ks, IDESC2,
                                    (i == 0 && ks == 0) ? 0u : 1u);
                    mma_bf16_ss_cg2(tmem, adh + 2 * ks, bdl + 2 * ks, IDESC2, 1u);
                    mma_bf16_ss_cg2(tmem, adl + 2 * ks, bdh + 2 * ks, IDESC2, 1u);
                }
                TC_COMMIT_MC2(sbase + SM_DONE + 8 * b, 3);
            }

            if (i + NBUF < NSTG) {
                // stage i's MMAs (reading this buffer in BOTH CTAs) must retire
                mbar_wait(sbase + SM_DONE + 8 * b, pdone[b]);
                pdone[b] ^= 1;
                issue(i + NBUF, b);
            }
        }
        // final stage retired (MMAs execute in order pair-wide)
        const int lb = (NSTG - 1) % NBUF;
        mbar_wait(sbase + SM_DONE + 8 * lb, pdone[lb]);
    }

    __syncthreads();
    TC_FENCE_AFTER();

    // epilogue: each CTA reads its own 128 rows (warps 0-3 = 32-row subparts)
    if (wid < 4) {
        float* crow = C + (size_t)(bm + wid * 32 + lane) * DIM + lcol;
#pragma unroll
        for (int cc = 0; cc < 8; cc++) {
            uint32_t r[32];
            LDTM_X32(r, tmem + cc * 32);
            TC_WAIT_LD();
            uint4* cp = (uint4*)(crow + cc * 32);
#pragma unroll
            for (int q = 0; q < 8; q++)
                cp[q] = make_uint4(r[4 * q], r[4 * q + 1], r[4 * q + 2], r[4 * q + 3]);
        }
        TC_FENCE_BEFORE();
    }

    __syncthreads();
    if (wid == 0) {
        TC_RELINQ2();
        TC_DEALLOC2(tmem, 256);
    }
    CLUSTER_SYNC();   // no CTA exits while peer ops could target its smem/barriers

#else  // ------- wmma fallback (family/generic targets; correctness net) -----
    using namespace nvcuda;
    const int GLDS = 40;
    __nv_bfloat16* sAh = (__nv_bfloat16*)smc;
    __nv_bfloat16* sAl = sAh + 128 * GLDS;
    __nv_bfloat16* sBh = sAl + 128 * GLDS;
    __nv_bfloat16* sBl = sBh + 128 * GLDS;

    const int wm = (wid & 1) * 64;
    const int wn = (wid >> 1) * 32;
    const int r0 = tid >> 2;
    const int c0 = (tid & 3) * 8;

    for (int half = 0; half < 2; half++) {
        const int bnh = bn + half * 128;
        wmma::fragment<wmma::accumulator, 16, 16, 16, float> acc[4][2];
#pragma unroll
        for (int i = 0; i < 4; i++)
#pragma unroll
            for (int j = 0; j < 2; j++) wmma::fill_fragment(acc[i][j], 0.0f);

        for (int k0 = 0; k0 < DIM; k0 += 32) {
            __syncthreads();
#pragma unroll
            for (int rr = 0; rr < 2; rr++) {
                int row = r0 + rr * 64;
                size_t ga = (size_t)(bm + row) * DIM + k0 + c0;
                size_t gb = (size_t)(bnh + row) * DIM + k0 + c0;
                *(uint4*)&sAh[row * GLDS + c0] = *(const uint4*)(Ah + ga);
                *(uint4*)&sAl[row * GLDS + c0] = *(const uint4*)(Al + ga);
                *(uint4*)&sBh[row * GLDS + c0] = *(const uint4*)(Bh + gb);
                *(uint4*)&sBl[row * GLDS + c0] = *(const uint4*)(Bl + gb);
            }
            __syncthreads();
#pragma unroll
            for (int kk = 0; kk < 32; kk += 16) {
                wmma::fragment<wmma::matrix_a, 16, 16, 16, __nv_bfloat16, wmma::row_major> fah[4], fal[4];
                wmma::fragment<wmma::matrix_b, 16, 16, 16, __nv_bfloat16, wmma::col_major> fbh[2], fbl[2];
#pragma unroll
                for (int i = 0; i < 4; i++) {
                    wmma::load_matrix_sync(fah[i], &sAh[(wm + i * 16) * GLDS + kk], GLDS);
                    wmma::load_matrix_sync(fal[i], &sAl[(wm + i * 16) * GLDS + kk], GLDS);
                }
#pragma unroll
                for (int j = 0; j < 2; j++) {
                    wmma::load_matrix_sync(fbh[j], &sBh[(wn + j * 16) * GLDS + kk], GLDS);
                    wmma::load_matrix_sync(fbl[j], &sBl[(wn + j * 16) * GLDS + kk], GLDS);
                }
#pragma unroll
                for (int i = 0; i < 4; i++)
#pragma unroll
                    for (int j = 0; j < 2; j++) {
                        wmma::mma_sync(acc[i][j], fah[i], fbh[j], acc[i][j]);
                        wmma::mma_sync(acc[i][j], fah[i], fbl[j], acc[i][j]);
                        wmma::mma_sync(acc[i][j], fal[i], fbh[j], acc[i][j]);
                    }
            }
        }
#pragma unroll
        for (int i = 0; i < 4; i++)
#pragma unroll
            for (int j = 0; j < 2; j++)
                wmma::store_matrix_sync(&C[(size_t)(bm + wm + i * 16) * DIM + lcol + half * 128 + wn + j * 16],
                                        acc[i][j], DIM, wmma::mem_row_major);
        __syncthreads();
    }
#endif
}

// ---------------------------------------------------------------------------
// Windowed attention, fused bias + RoPE; 4x4 score / 4x5 PV register microtiles
// ---------------------------------------------------------------------------
__global__ __launch_bounds__(256)
void attn_win(const float* __restrict__ cosp, const float* __restrict__ sinp,
              const float* __restrict__ bq, const float* __restrict__ bk,
              const float* __restrict__ bv)
{
    extern __shared__ float sm[];
    float* qs = sm;
    float* ks = qs + WIN * HDP;
    float* vs = ks + WIN * HDP;
    float* sc = vs + WIN * HDP;

    const int w = blockIdx.x;
    const int h = blockIdx.y;
    const int tid = threadIdx.x;
    const size_t base = (size_t)(w * WIN) * DIM + (size_t)h * HD;

    for (int idx = tid; idx < WIN * (HD / 2); idx += 256) {
        int row = idx / (HD / 2);
        int d   = idx % (HD / 2);
        int s   = w * WIN + row;
        float c1 = cosp[s * HD + d],          s1 = sinp[s * HD + d];
        float c2 = cosp[s * HD + d + HD / 2], s2 = sinp[s * HD + d + HD / 2];
        size_t o1 = base + (size_t)row * DIM + d;
        size_t o2 = o1 + HD / 2;

        float q1 = g_q[o1] + bq[h * HD + d];
        float q2 = g_q[o2] + bq[h * HD + d + HD / 2];
        qs[row * HDP + d]          = q1 * c1 - q2 * s1;
        qs[row * HDP + d + HD / 2] = q2 * c2 + q1 * s2;

        float k1 = g_k[o1] + bk[h * HD + d];
        float k2 = g_k[o2] + bk[h * HD + d + HD / 2];
        ks[row * HDP + d]          = k1 * c1 - k2 * s1;
        ks[row * HDP + d + HD / 2] = k2 * c2 + k1 * s2;
    }
    for (int idx = tid; idx < WIN * (HD / 4); idx += 256) {
        int row = idx / (HD / 4);
        int col = (idx % (HD / 4)) * 4;
        size_t g = base + (size_t)row * DIM + col;
        float4 vv = *(const float4*)(g_v + g);
        vv.x += bv[h * HD + col + 0];
        vv.y += bv[h * HD + col + 1];
        vv.z += bv[h * HD + col + 2];
        vv.w += bv[h * HD + col + 3];
        *(float4*)(vs + row * HDP + col) = vv;
    }
    __syncthreads();

    // scores: 4x4 microtile per thread (16x16 thread grid)
    const float scale = 0.11180339887498949f;
    {
        const int ti = (tid >> 4) * 4;
        const int tj = (tid & 15) * 4;
        float acc[4][4];
#pragma unroll
        for (int r = 0; r < 4; r++)
#pragma unroll
            for (int c = 0; c < 4; c++) acc[r][c] = 0.f;

        for (int d = 0; d < HD; d += 4) {
            float4 qv[4], kv[4];
#pragma unroll
            for (int r = 0; r < 4; r++) qv[r] = *(const float4*)(qs + (ti + r) * HDP + d);
#pragma unroll
            for (int c = 0; c < 4; c++) kv[c] = *(const float4*)(ks + (tj + c) * HDP + d);
#pragma unroll
            for (int r = 0; r < 4; r++)
#pragma unroll
                for (int c = 0; c < 4; c++)
                    acc[r][c] += qv[r].x * kv[c].x + qv[r].y * kv[c].y
                               + qv[r].z * kv[c].z + qv[r].w * kv[c].w;
        }
#pragma unroll
        for (int r = 0; r < 4; r++)
#pragma unroll
            for (int c = 0; c < 4; c++)
                sc[(ti + r) * SCP + tj + c] = acc[r][c] * scale;
    }
    __syncthreads();

    if (tid < WIN) {
        float m = -1e30f;
        for (int j = 0; j < WIN; j++) m = fmaxf(m, sc[tid * SCP + j]);
        float sum = 0.f;
        for (int j = 0; j < WIN; j++) {
            float e = __expf(sc[tid * SCP + j] - m);
            sc[tid * SCP + j] = e;
            sum += e;
        }
        float inv = 1.f / sum;
        for (int j = 0; j < WIN; j++) sc[tid * SCP + j] *= inv;
    }
    __syncthreads();

    // P@V: 4 rows x 5 cols per thread; write bf16 hi/lo split
    {
        const int pr = (tid >> 4) * 4;
        const int pc = (tid & 15) * 5;
        float o[4][5];
#pragma unroll
        for (int r = 0; r < 4; r++)
#pragma unroll
            for (int c = 0; c < 5; c++) o[r][c] = 0.f;

        for (int j = 0; j < WIN; j++) {
            float sv[4], vv[5];
#pragma unroll
            for (int r = 0; r < 4; r++) sv[r] = sc[(pr + r) * SCP + j];
#pragma unroll
            for (int c = 0; c < 5; c++) vv[c] = vs[j * HDP + pc + c];
#pragma unroll
            for (int r = 0; r < 4; r++)
#pragma unroll
                for (int c = 0; c < 5; c++) o[r][c] += sv[r] * vv[c];
        }
#pragma unroll
        for (int r = 0; r < 4; r++) {
            size_t ob = base + (size_t)(pr + r) * DIM + pc;
#pragma unroll
            for (int c = 0; c < 5; c++) {
                __nv_bfloat16 hi = __float2bfloat16(o[r][c]);
                g_ahi[ob + c] = hi;
                g_alo[ob + c] = __float2bfloat16(o[r][c] - __bfloat162float(hi));
            }
        }
    }
}

// ---------------------------------------------------------------------------
__global__ void bias_add(float* __restrict__ out, const float* __restrict__ bp)
{
    int i = blockIdx.x * blockDim.x + threadIdx.x;
    float4 v = ((float4*)out)[i];
    int col = (i * 4) % DIM;
    v.x += bp[col + 0];
    v.y += bp[col + 1];
    v.z += bp[col + 2];
    v.w += bp[col + 3];
    ((float4*)out)[i] = v;
}

// ---------------------------------------------------------------------------
typedef CUresult (*PFN_tmap_encode)(
    CUtensorMap*, CUtensorMapDataType, cuuint32_t, void*,
    const cuuint64_t*, const cuuint64_t*, const cuuint32_t*, const cuuint32_t*,
    CUtensorMapInterleave, CUtensorMapSwizzle, CUtensorMapL2promotion,
    CUtensorMapFloatOOBfill);

static void encode_map(PFN_tmap_encode enc, CUtensorMap* m, void* base, uint64_t rows)
{
    cuuint64_t dims[2]    = {DIM, rows};
    cuuint64_t strides[1] = {DIM * 2};           // bytes
    cuuint32_t box[2]     = {64, 128};           // 128B x 128 rows (SW128 atom)
    cuuint32_t es[2]      = {1, 1};
    enc(m, CU_TENSOR_MAP_DATA_TYPE_BFLOAT16, 2, base, dims, strides, box, es,
        CU_TENSOR_MAP_INTERLEAVE_NONE, CU_TENSOR_MAP_SWIZZLE_128B,
        CU_TENSOR_MAP_L2_PROMOTION_L2_128B, CU_TENSOR_MAP_FLOAT_OOB_FILL_NONE);
}

extern "C" void kernel_launch(void* const* d_in, const int* in_sizes, int n_in,
                              void* d_out, int out_size)
{
    const float* hs   = (const float*)d_in[0];
    const float* cosp = (const float*)d_in[1];
    const float* sinp = (const float*)d_in[2];
    const float* Wq   = (const float*)d_in[3];
    const float* bq   = (const float*)d_in[4];
    const float* Wk   = (const float*)d_in[5];
    const float* bk   = (const float*)d_in[6];
    const float* Wv   = (const float*)d_in[7];
    const float* bv   = (const float*)d_in[8];
    const float* Wp   = (const float*)d_in[9];
    const float* bp   = (const float*)d_in[10];
    float* out = (float*)d_out;

    float *pq, *pk, *pv;
    __nv_bfloat16 *pah, *pal, *pwh, *pwl;
    cudaGetSymbolAddress((void**)&pq,  g_q);
    cudaGetSymbolAddress((void**)&pk,  g_k);
    cudaGetSymbolAddress((void**)&pv,  g_v);
    cudaGetSymbolAddress((void**)&pah, g_ahi);
    cudaGetSymbolAddress((void**)&pal, g_alo);
    cudaGetSymbolAddress((void**)&pwh, g_whi);
    cudaGetSymbolAddress((void**)&pwl, g_wlo);

    PFN_tmap_encode enc = nullptr;
    cudaDriverEntryPointQueryResult qr;
    cudaGetDriverEntryPoint("cuTensorMapEncodeTiled", (void**)&enc,
                            cudaEnableDefault, &qr);
    CUtensorMap tmAh, tmAl, tmBh, tmBl;
    encode_map(enc, &tmAh, pah, SEQ);
    encode_map(enc, &tmAl, pal, SEQ);
    encode_map(enc, &tmBh, pwh, 3 * DIM);
    encode_map(enc, &tmBl, pwl, 3 * DIM);

    const int nA4 = SEQ * DIM / 4;
    const int nW4 = DIM * DIM / 4;

    cudaFuncSetAttribute(gemm_tc, cudaFuncAttributeMaxDynamicSharedMemorySize, SMEM_GEMM);

    split_kernel<<<(nA4 + 255) / 256, 256>>>(hs, pah, pal, nA4);
    split_kernel<<<(nW4 + 255) / 256, 256>>>(Wq, pwh,                 pwl,                 nW4);
    split_kernel<<<(nW4 + 255) / 256, 256>>>(Wk, pwh + DIM * DIM,     pwl + DIM * DIM,     nW4);
    split_kernel<<<(nW4 + 255) / 256, 256>>>(Wv, pwh + 2 * DIM * DIM, pwl + 2 * DIM * DIM, nW4);

    // fused QKV GEMM: grid (128, 15), cluster (2,1,1) pairs along M (x)
    gemm_tc<<<dim3(SEQ / TM, 3 * DIM / TN), 256, SMEM_GEMM>>>(
        tmAh, tmAl, tmBh, tmBl, pah, pal, pwh, pwl, pq, pk, pv, 1);

    const int smem = (3 * WIN * HDP + WIN * SCP) * (int)sizeof(float);
    cudaFuncSetAttribute(attn_win, cudaFuncAttributeMaxDynamicSharedMemorySize, smem);
    attn_win<<<dim3(NWIN, NH), 256, smem>>>(cosp, sinp, bq, bk, bv);

    split_kernel<<<(nW4 + 255) / 256, 256>>>(Wp, pwh, pwl, nW4);
    gemm_tc<<<dim3(SEQ / TM, DIM / TN), 256, SMEM_GEMM>>>(
        tmAh, tmAl, tmBh, tmBl, pah, pal, pwh, pwl, out, out, out, 0);
    bias_add<<<nA4 / 256, 256>>>(out, bp);
}

// round 9
// speedup vs baseline: 1.1272x; 1.1272x over previous
#include <cuda_runtime.h>
#include <cuda.h>
#include <cuda_bf16.h>
#include <mma.h>
#include <cstdint>

#define SEQ   16384
#define DIM   1280
#define NH    16
#define HD    80
#define WIN   64
#define NWIN  (SEQ / WIN)
#define HDP   84
#define SCP   65

// tcgen05 cg2 GEMM tiling: cluster of 2 CTAs (along x) computes 256x256 C tile
#define TM    128          // M rows per CTA (cluster M = 256)
#define TN    256          // N tile (each CTA holds N/2=128 B rows)
#define TKB   128          // K-chunk bytes per row (64 bf16) = SW128 row
#define TKE   64           // K-chunk elements
#define NSTG  (DIM / TKE)  // 20 k-stages
#define NBUF  3

// smem layout (dynamic)
#define SM_TMEM   0
#define SM_FULL   8        // full[0..2] at 8,16,24 (leader only)
#define SM_DONE   32       // done[0..2] at 32,40,48
#define SM_BUF    1024
#define AB_QTR    16384                      // 128 rows x 128B (one operand slice)
#define STAGE_BYTES (4 * AB_QTR)             // 64 KB per CTA per stage
#define SMEM_GEMM (SM_BUF + NBUF * STAGE_BYTES) // 197,632 B
#define STAGE_TX  (2 * STAGE_BYTES)          // both CTAs' tx land on leader barrier

// Arch-specific tcgen05 (TMEM ld/st) only exists on sm_10xa targets.
#if defined(__CUDA_ARCH__) && (defined(__CUDA_ARCH_FEAT_SM103_ALL) || defined(__CUDA_ARCH_FEAT_SM100_ALL))
#define TC_PATH 1
#else
#define TC_PATH 0
#endif

// ---------------------------------------------------------------------------
// Scratch
// ---------------------------------------------------------------------------
__device__ float g_q[SEQ * DIM];
__device__ float g_k[SEQ * DIM];
__device__ float g_v[SEQ * DIM];
__device__ __nv_bfloat16 g_ahi[SEQ * DIM];
__device__ __nv_bfloat16 g_alo[SEQ * DIM];
__device__ __nv_bfloat16 g_whi[3 * DIM * DIM];   // Wq|Wk|Wv stacked (Wp reuses rows 0..1279)
__device__ __nv_bfloat16 g_wlo[3 * DIM * DIM];

#if TC_PATH
// ---------------------------------------------------------------------------
// PTX helpers (sm_103a only)
// ---------------------------------------------------------------------------
__device__ __forceinline__ uint32_t smem_u32(const void* p) {
    uint32_t a;
    asm("{ .reg .u64 t; cvta.to.shared.u64 t, %1; cvt.u32.u64 %0, t; }"
        : "=r"(a) : "l"(p));
    return a;
}

__device__ __forceinline__ uint32_t ctarank() {
    uint32_t r;
    asm("mov.u32 %0, %%cluster_ctarank;" : "=r"(r));
    return r;
}

#define MBAR_INIT(addr, cnt) \
    asm volatile("mbarrier.init.shared.b64 [%0], %1;" :: "r"(addr), "r"(cnt) : "memory")

#define MBAR_EXPECT_TX(addr, tx) \
    asm volatile("mbarrier.arrive.expect_tx.shared.b64 _, [%0], %1;" :: "r"(addr), "r"(tx) : "memory")

__device__ __forceinline__ void mbar_wait(uint32_t mbar, uint32_t phase) {
    asm volatile(
        "{\n\t.reg .pred P;\n\t"
        "WL_%=:\n\t"
        "mbarrier.try_wait.parity.acquire.cta.shared::cta.b64 P, [%0], %1, 0x989680;\n\t"
        "@P bra WD_%=;\n\t"
        "bra WL_%=;\n\t"
        "WD_%=:\n\t}"
        :: "r"(mbar), "r"(phase) : "memory");
}

#define CLUSTER_SYNC() do { \
    asm volatile("barrier.cluster.arrive.aligned;" ::: "memory"); \
    asm volatile("barrier.cluster.wait.aligned;" ::: "memory"); \
} while (0)

// 2D TMA cg2 load: both CTAs execute; complete_tx lands on LEADER's barrier
// (bit 24 of the barrier address cleared = rank-0 CTA in the pair).
__device__ __forceinline__ void tma2d_cg2(uint32_t saddr, const void* tmap, int x, int y,
                                          uint32_t mbar) {
    asm volatile(
        "{\n\t.reg .b32 lb;\n\tand.b32 lb, %4, 0xFEFFFFFF;\n\t"
        "cp.async.bulk.tensor.2d.cta_group::2.shared::cluster.global.tile"
        ".mbarrier::complete_tx::bytes [%0], [%1, {%2, %3}], [lb];\n\t}"
        :: "r"(saddr), "l"(tmap), "r"(x), "r"(y), "r"(mbar) : "memory");
}

// SW128 K-major smem descriptor: layout=2, version=1, SBO=64, LBO=1
__device__ __forceinline__ uint64_t mk_desc(uint32_t addr) {
    return ((uint64_t)2 << 61) | ((uint64_t)1 << 46) | ((uint64_t)64 << 32) |
           ((uint64_t)1 << 16) | (uint64_t)((addr >> 4) & 0x3FFF);
}

// cg2 bf16 SS MMA: D[256,256] fp32 += A[256,16] * B[256,16]^T (pair-wide)
__device__ __forceinline__ void mma_bf16_ss_cg2(uint32_t d, uint64_t ad, uint64_t bd,
                                                uint32_t idesc, uint32_t en) {
    asm volatile(
        "{\n\t.reg .pred p;\n\tsetp.ne.u32 p, %5, 0;\n\t"
        "tcgen05.mma.cta_group::2.kind::f16 [%0], %1, %2, %3, "
        "{%4, %4, %4, %4, %4, %4, %4, %4}, p;\n\t}"
        :: "r"(d), "l"(ad), "l"(bd), "r"(idesc), "r"(0u), "r"(en) : "memory");
}

// cg2 commit, arriving at the same mbarrier offset in BOTH cluster CTAs
#define TC_COMMIT_MC2(mbar, mask) \
    asm volatile("tcgen05.commit.cta_group::2.mbarrier::arrive::one.shared::cluster" \
                 ".multicast::cluster.b64 [%0], %1;" :: "r"(mbar), "h"((uint16_t)(mask)) : "memory")
#define TC_ALLOC2(slot, n) \
    asm volatile("tcgen05.alloc.cta_group::2.sync.aligned.shared::cta.b32 [%0], %1;" \
                 :: "r"(slot), "r"(n) : "memory")
#define TC_RELINQ2() \
    asm volatile("tcgen05.relinquish_alloc_permit.cta_group::2.sync.aligned;")
#define TC_DEALLOC2(t, n) \
    asm volatile("tcgen05.dealloc.cta_group::2.sync.aligned.b32 %0, %1;" :: "r"(t), "r"(n))
#define TC_FENCE_AFTER()  asm volatile("tcgen05.fence::after_thread_sync;" ::: "memory")
#define TC_FENCE_BEFORE() asm volatile("tcgen05.fence::before_thread_sync;" ::: "memory")
#define TC_WAIT_LD() asm volatile("tcgen05.wait::ld.sync.aligned;" ::: "memory")

#define LDTM_X32(r, addr) \
    asm volatile("tcgen05.ld.sync.aligned.32x32b.x32.b32 " \
        "{%0,%1,%2,%3,%4,%5,%6,%7,%8,%9,%10,%11,%12,%13,%14,%15," \
        "%16,%17,%18,%19,%20,%21,%22,%23,%24,%25,%26,%27,%28,%29,%30,%31}, [%32];" \
        : "=r"((r)[0]),"=r"((r)[1]),"=r"((r)[2]),"=r"((r)[3]), \
          "=r"((r)[4]),"=r"((r)[5]),"=r"((r)[6]),"=r"((r)[7]), \
          "=r"((r)[8]),"=r"((r)[9]),"=r"((r)[10]),"=r"((r)[11]), \
          "=r"((r)[12]),"=r"((r)[13]),"=r"((r)[14]),"=r"((r)[15]), \
          "=r"((r)[16]),"=r"((r)[17]),"=r"((r)[18]),"=r"((r)[19]), \
          "=r"((r)[20]),"=r"((r)[21]),"=r"((r)[22]),"=r"((r)[23]), \
          "=r"((r)[24]),"=r"((r)[25]),"=r"((r)[26]),"=r"((r)[27]), \
          "=r"((r)[28]),"=r"((r)[29]),"=r"((r)[30]),"=r"((r)[31]) \
        : "r"(addr))

// idesc: fp32 accum, bf16 a/b, N=256, M=256 (cg2 pair-wide)
#define IDESC2 ((1u << 4) | (1u << 7) | (1u << 10) | ((TN / 8) << 17) | (16u << 24))
#endif  // TC_PATH

// ---------------------------------------------------------------------------
// fp32 -> bf16 hi + residual lo
// ---------------------------------------------------------------------------
__global__ void split_kernel(const float* __restrict__ src,
                             __nv_bfloat16* __restrict__ hi,
                             __nv_bfloat16* __restrict__ lo, int n4)
{
    int i = blockIdx.x * blockDim.x + threadIdx.x;
    if (i >= n4) return;
    float4 v = ((const float4*)src)[i];
    __nv_bfloat16 h0 = __float2bfloat16(v.x);
    __nv_bfloat16 h1 = __float2bfloat16(v.y);
    __nv_bfloat16 h2 = __float2bfloat16(v.z);
    __nv_bfloat16 h3 = __float2bfloat16(v.w);
    __nv_bfloat16 l0 = __float2bfloat16(v.x - __bfloat162float(h0));
    __nv_bfloat16 l1 = __float2bfloat16(v.y - __bfloat162float(h1));
    __nv_bfloat16 l2 = __float2bfloat16(v.z - __bfloat162float(h2));
    __nv_bfloat16 l3 = __float2bfloat16(v.w - __bfloat162float(h3));
    __nv_bfloat162* hp = (__nv_bfloat162*)hi;
    __nv_bfloat162* lp = (__nv_bfloat162*)lo;
    hp[2 * i]     = __nv_bfloat162(h0, h1);
    hp[2 * i + 1] = __nv_bfloat162(h2, h3);
    lp[2 * i]     = __nv_bfloat162(l0, l1);
    lp[2 * i + 1] = __nv_bfloat162(l2, l3);
}

// ---------------------------------------------------------------------------
// tcgen05 cg2 bf16x3 GEMM. Cluster (2,1,1): pair along x computes C[256 x 256].
// Lagged done-wait pipeline: at iter i we commit stage i, then wait on stage
// i-1's done (already retired) to refill its buffer -> tensor queue never
// drains. Optional bias folded into epilogue.
// ---------------------------------------------------------------------------
__global__ __launch_bounds__(256, 1) __cluster_dims__(2, 1, 1)
void gemm_tc(const __grid_constant__ CUtensorMap tmAh,
             const __grid_constant__ CUtensorMap tmAl,
             const __grid_constant__ CUtensorMap tmBh,
             const __grid_constant__ CUtensorMap tmBl,
             const __nv_bfloat16* __restrict__ Ah,
             const __nv_bfloat16* __restrict__ Al,
             const __nv_bfloat16* __restrict__ Bh,
             const __nv_bfloat16* __restrict__ Bl,
             float* cq, float* ck, float* cv,
             const float* __restrict__ bias, int fused)
{
    extern __shared__ char smc[];
    const int tid = threadIdx.x;
    const int wid = tid >> 5;
    const int bm = blockIdx.x * TM;       // this CTA's own 128 M rows (pairs along x)
    const int bn = blockIdx.y * TN;

    float* C;
    int lcol;
    if (fused) {
        int mtx = blockIdx.y / 5;
        C = (mtx == 0) ? cq : (mtx == 1) ? ck : cv;
        lcol = (blockIdx.y % 5) * TN;
    } else {
        C = cq;
        lcol = bn;
    }

#if TC_PATH
    const int lane = tid & 31;
    const uint32_t sbase = smem_u32(smc);
    const uint32_t rank = ctarank();

    if (tid == 0) {
#pragma unroll
        for (int s = 0; s < NBUF; s++) {
            MBAR_INIT(sbase + SM_FULL + 8 * s, 1);   // leader expect_tx is sole arrival
            MBAR_INIT(sbase + SM_DONE + 8 * s, 1);   // one cg2 commit arrival
        }
    }
    if (wid == 0) {
        TC_ALLOC2(sbase + SM_TMEM, 256);
        TC_RELINQ2();
    }
    __syncthreads();
    CLUSTER_SYNC();   // mbarriers + alloc visible pair-wide before cg2 TMA

    uint32_t tmem;
    asm volatile("ld.shared.b32 %0, [%1];" : "=r"(tmem) : "r"(sbase + SM_TMEM));

    if (tid == 0) {
        const int brow = bn + (int)rank * 128;   // this CTA's distinct B half

        auto issue = [&](int i, int b) {
            const uint32_t buf = sbase + SM_BUF + b * STAGE_BYTES;
            const uint32_t fullb = sbase + SM_FULL + 8 * b;
            const int x = i * TKE;
            if (rank == 0) MBAR_EXPECT_TX(fullb, STAGE_TX);
            tma2d_cg2(buf,              &tmAh, x, bm,   fullb);
            tma2d_cg2(buf + AB_QTR,     &tmAl, x, bm,   fullb);
            tma2d_cg2(buf + 2 * AB_QTR, &tmBh, x, brow, fullb);
            tma2d_cg2(buf + 3 * AB_QTR, &tmBl, x, brow, fullb);
        };

        int pfull[NBUF] = {0, 0, 0}, pdone[NBUF] = {0, 0, 0};
        issue(0, 0);
        issue(1, 1);
        issue(2, 2);

        for (int i = 0; i < NSTG; i++) {
            const int b = i % NBUF;

            if (rank == 0) {
                mbar_wait(sbase + SM_FULL + 8 * b, pfull[b]);
                pfull[b] ^= 1;

                const uint32_t bufb = sbase + SM_BUF + b * STAGE_BYTES;
                uint64_t adh = mk_desc(bufb);
                uint64_t adl = mk_desc(bufb + AB_QTR);
                uint64_t bdh = mk_desc(bufb + 2 * AB_QTR);
                uint64_t bdl = mk_desc(bufb + 3 * AB_QTR);
#pragma unroll
                for (int ks = 0; ks < 4; ks++) {
                    mma_bf16_ss_cg2(tmem, adh + 2 * ks, bdh + 2 * ks, IDESC2,
                                    (i == 0 && ks == 0) ? 0u : 1u);
                    mma_bf16_ss_cg2(tmem, adh + 2 * ks, bdl + 2 * ks, IDESC2, 1u);
                    mma_bf16_ss_cg2(tmem, adl + 2 * ks, bdh + 2 * ks, IDESC2, 1u);
                }
                TC_COMMIT_MC2(sbase + SM_DONE + 8 * b, 3);
            }

            // LAGGED refill: stage i-1's MMAs were committed a full stage ago;
            // wait that (nearly-always-passed) barrier and refill its buffer.
            const int j = i - 1;
            if (j >= 0 && j + NBUF < NSTG) {
                const int jb = j % NBUF;
                mbar_wait(sbase + SM_DONE + 8 * jb, pdone[jb]);
                pdone[jb] ^= 1;
                issue(j + NBUF, jb);
            }
        }
        // final stage retired (MMAs execute in order pair-wide)
        const int lb = (NSTG - 1) % NBUF;
        mbar_wait(sbase + SM_DONE + 8 * lb, pdone[lb]);
    }

    __syncthreads();
    TC_FENCE_AFTER();

    // epilogue: each CTA reads its own 128 rows (warps 0-3 = 32-row subparts)
    if (wid < 4) {
        float* crow = C + (size_t)(bm + wid * 32 + lane) * DIM + lcol;
#pragma unroll
        for (int cc = 0; cc < 8; cc++) {
            uint32_t r[32];
            LDTM_X32(r, tmem + cc * 32);
            TC_WAIT_LD();
            if (!fused) {
                float4* cp = (float4*)(crow + cc * 32);
#pragma unroll
                for (int q = 0; q < 8; q++) {
                    float4 bb = *(const float4*)(bias + lcol + cc * 32 + q * 4);
                    float4 v;
                    v.x = __uint_as_float(r[4 * q + 0]) + bb.x;
                    v.y = __uint_as_float(r[4 * q + 1]) + bb.y;
                    v.z = __uint_as_float(r[4 * q + 2]) + bb.z;
                    v.w = __uint_as_float(r[4 * q + 3]) + bb.w;
                    cp[q] = v;
                }
            } else {
                uint4* cp = (uint4*)(crow + cc * 32);
#pragma unroll
                for (int q = 0; q < 8; q++)
                    cp[q] = make_uint4(r[4 * q], r[4 * q + 1], r[4 * q + 2], r[4 * q + 3]);
            }
        }
        TC_FENCE_BEFORE();
    }

    __syncthreads();
    if (wid == 0) {
        TC_DEALLOC2(tmem, 256);
    }
    CLUSTER_SYNC();   // no CTA exits while peer ops could target its smem/barriers

#else  // ------- wmma fallback (family/generic targets; correctness net) -----
    using namespace nvcuda;
    const int GLDS = 40;
    __nv_bfloat16* sAh = (__nv_bfloat16*)smc;
    __nv_bfloat16* sAl = sAh + 128 * GLDS;
    __nv_bfloat16* sBh = sAl + 128 * GLDS;
    __nv_bfloat16* sBl = sBh + 128 * GLDS;

    const int wm = (wid & 1) * 64;
    const int wn = (wid >> 1) * 32;
    const int r0 = tid >> 2;
    const int c0 = (tid & 3) * 8;

    for (int half = 0; half < 2; half++) {
        const int bnh = bn + half * 128;
        wmma::fragment<wmma::accumulator, 16, 16, 16, float> acc[4][2];
#pragma unroll
        for (int i = 0; i < 4; i++)
#pragma unroll
            for (int j = 0; j < 2; j++) wmma::fill_fragment(acc[i][j], 0.0f);

        for (int k0 = 0; k0 < DIM; k0 += 32) {
            __syncthreads();
#pragma unroll
            for (int rr = 0; rr < 2; rr++) {
                int row = r0 + rr * 64;
                size_t ga = (size_t)(bm + row) * DIM + k0 + c0;
                size_t gb = (size_t)(bnh + row) * DIM + k0 + c0;
                *(uint4*)&sAh[row * GLDS + c0] = *(const uint4*)(Ah + ga);
                *(uint4*)&sAl[row * GLDS + c0] = *(const uint4*)(Al + ga);
                *(uint4*)&sBh[row * GLDS + c0] = *(const uint4*)(Bh + gb);
                *(uint4*)&sBl[row * GLDS + c0] = *(const uint4*)(Bl + gb);
            }
            __syncthreads();
#pragma unroll
            for (int kk = 0; kk < 32; kk += 16) {
                wmma::fragment<wmma::matrix_a, 16, 16, 16, __nv_bfloat16, wmma::row_major> fah[4], fal[4];
                wmma::fragment<wmma::matrix_b, 16, 16, 16, __nv_bfloat16, wmma::col_major> fbh[2], fbl[2];
#pragma unroll
                for (int i = 0; i < 4; i++) {
                    wmma::load_matrix_sync(fah[i], &sAh[(wm + i * 16) * GLDS + kk], GLDS);
                    wmma::load_matrix_sync(fal[i], &sAl[(wm + i * 16) * GLDS + kk], GLDS);
                }
#pragma unroll
                for (int j = 0; j < 2; j++) {
                    wmma::load_matrix_sync(fbh[j], &sBh[(wn + j * 16) * GLDS + kk], GLDS);
                    wmma::load_matrix_sync(fbl[j], &sBl[(wn + j * 16) * GLDS + kk], GLDS);
                }
#pragma unroll
                for (int i = 0; i < 4; i++)
#pragma unroll
                    for (int j = 0; j < 2; j++) {
                        wmma::mma_sync(acc[i][j], fah[i], fbh[j], acc[i][j]);
                        wmma::mma_sync(acc[i][j], fah[i], fbl[j], acc[i][j]);
                        wmma::mma_sync(acc[i][j], fal[i], fbh[j], acc[i][j]);
                    }
            }
        }
#pragma unroll
        for (int i = 0; i < 4; i++)
#pragma unroll
            for (int j = 0; j < 2; j++)
                wmma::store_matrix_sync(&C[(size_t)(bm + wm + i * 16) * DIM + lcol + half * 128 + wn + j * 16],
                                        acc[i][j], DIM, wmma::mem_row_major);
        __syncthreads();
    }
    // bias fold (fallback path)
    if (!fused && bias) {
        for (int idx = tid; idx < TM * TN; idx += 256) {
            int row = idx / TN, col = idx % TN;
            C[(size_t)(bm + row) * DIM + lcol + col] += bias[lcol + col];
        }
    }
#endif
}

// ---------------------------------------------------------------------------
// Windowed attention, fused bias + RoPE; 4x4 score / 4x5 PV register microtiles
// ---------------------------------------------------------------------------
__global__ __launch_bounds__(256)
void attn_win(const float* __restrict__ cosp, const float* __restrict__ sinp,
              const float* __restrict__ bq, const float* __restrict__ bk,
              const float* __restrict__ bv)
{
    extern __shared__ float sm[];
    float* qs = sm;
    float* ks = qs + WIN * HDP;
    float* vs = ks + WIN * HDP;
    float* sc = vs + WIN * HDP;

    const int w = blockIdx.x;
    const int h = blockIdx.y;
    const int tid = threadIdx.x;
    const size_t base = (size_t)(w * WIN) * DIM + (size_t)h * HD;

    for (int idx = tid; idx < WIN * (HD / 2); idx += 256) {
        int row = idx / (HD / 2);
        int d   = idx % (HD / 2);
        int s   = w * WIN + row;
        float c1 = cosp[s * HD + d],          s1 = sinp[s * HD + d];
        float c2 = cosp[s * HD + d + HD / 2], s2 = sinp[s * HD + d + HD / 2];
        size_t o1 = base + (size_t)row * DIM + d;
        size_t o2 = o1 + HD / 2;

        float q1 = g_q[o1] + bq[h * HD + d];
        float q2 = g_q[o2] + bq[h * HD + d + HD / 2];
        qs[row * HDP + d]          = q1 * c1 - q2 * s1;
        qs[row * HDP + d + HD / 2] = q2 * c2 + q1 * s2;

        float k1 = g_k[o1] + bk[h * HD + d];
        float k2 = g_k[o2] + bk[h * HD + d + HD / 2];
        ks[row * HDP + d]          = k1 * c1 - k2 * s1;
        ks[row * HDP + d + HD / 2] = k2 * c2 + k1 * s2;
    }
    for (int idx = tid; idx < WIN * (HD / 4); idx += 256) {
        int row = idx / (HD / 4);
        int col = (idx % (HD / 4)) * 4;
        size_t g = base + (size_t)row * DIM + col;
        float4 vv = *(const float4*)(g_v + g);
        vv.x += bv[h * HD + col + 0];
        vv.y += bv[h * HD + col + 1];
        vv.z += bv[h * HD + col + 2];
        vv.w += bv[h * HD + col + 3];
        *(float4*)(vs + row * HDP + col) = vv;
    }
    __syncthreads();

    // scores: 4x4 microtile per thread (16x16 thread grid)
    const float scale = 0.11180339887498949f;
    {
        const int ti = (tid >> 4) * 4;
        const int tj = (tid & 15) * 4;
        float acc[4][4];
#pragma unroll
        for (int r = 0; r < 4; r++)
#pragma unroll
            for (int c = 0; c < 4; c++) acc[r][c] = 0.f;

        for (int d = 0; d < HD; d += 4) {
            float4 qv[4], kv[4];
#pragma unroll
            for (int r = 0; r < 4; r++) qv[r] = *(const float4*)(qs + (ti + r) * HDP + d);
#pragma unroll
            for (int c = 0; c < 4; c++) kv[c] = *(const float4*)(ks + (tj + c) * HDP + d);
#pragma unroll
            for (int r = 0; r < 4; r++)
#pragma unroll
                for (int c = 0; c < 4; c++)
                    acc[r][c] += qv[r].x * kv[c].x + qv[r].y * kv[c].y
                               + qv[r].z * kv[c].z + qv[r].w * kv[c].w;
        }
#pragma unroll
        for (int r = 0; r < 4; r++)
#pragma unroll
            for (int c = 0; c < 4; c++)
                sc[(ti + r) * SCP + tj + c] = acc[r][c] * scale;
    }
    __syncthreads();

    if (tid < WIN) {
        float m = -1e30f;
        for (int j = 0; j < WIN; j++) m = fmaxf(m, sc[tid * SCP + j]);
        float sum = 0.f;
        for (int j = 0; j < WIN; j++) {
            float e = __expf(sc[tid * SCP + j] - m);
            sc[tid * SCP + j] = e;
            sum += e;
        }
        float inv = 1.f / sum;
        for (int j = 0; j < WIN; j++) sc[tid * SCP + j] *= inv;
    }
    __syncthreads();

    // P@V: 4 rows x 5 cols per thread; write bf16 hi/lo split
    {
        const int pr = (tid >> 4) * 4;
        const int pc = (tid & 15) * 5;
        float o[4][5];
#pragma unroll
        for (int r = 0; r < 4; r++)
#pragma unroll
            for (int c = 0; c < 5; c++) o[r][c] = 0.f;

        for (int j = 0; j < WIN; j++) {
            float sv[4], vv[5];
#pragma unroll
            for (int r = 0; r < 4; r++) sv[r] = sc[(pr + r) * SCP + j];
#pragma unroll
            for (int c = 0; c < 5; c++) vv[c] = vs[j * HDP + pc + c];
#pragma unroll
            for (int r = 0; r < 4; r++)
#pragma unroll
                for (int c = 0; c < 5; c++) o[r][c] += sv[r] * vv[c];
        }
#pragma unroll
        for (int r = 0; r < 4; r++) {
            size_t ob = base + (size_t)(pr + r) * DIM + pc;
#pragma unroll
            for (int c = 0; c < 5; c++) {
                __nv_bfloat16 hi = __float2bfloat16(o[r][c]);
                g_ahi[ob + c] = hi;
                g_alo[ob + c] = __float2bfloat16(o[r][c] - __bfloat162float(hi));
            }
        }
    }
}

// ---------------------------------------------------------------------------
typedef CUresult (*PFN_tmap_encode)(
    CUtensorMap*, CUtensorMapDataType, cuuint32_t, void*,
    const cuuint64_t*, const cuuint64_t*, const cuuint32_t*, const cuuint32_t*,
    CUtensorMapInterleave, CUtensorMapSwizzle, CUtensorMapL2promotion,
    CUtensorMapFloatOOBfill);

static void encode_map(PFN_tmap_encode enc, CUtensorMap* m, void* base, uint64_t rows)
{
    cuuint64_t dims[2]    = {DIM, rows};
    cuuint64_t strides[1] = {DIM * 2};           // bytes
    cuuint32_t box[2]     = {64, 128};           // 128B x 128 rows (SW128 atom)
    cuuint32_t es[2]      = {1, 1};
    enc(m, CU_TENSOR_MAP_DATA_TYPE_BFLOAT16, 2, base, dims, strides, box, es,
        CU_TENSOR_MAP_INTERLEAVE_NONE, CU_TENSOR_MAP_SWIZZLE_128B,
        CU_TENSOR_MAP_L2_PROMOTION_L2_128B, CU_TENSOR_MAP_FLOAT_OOB_FILL_NONE);
}

extern "C" void kernel_launch(void* const* d_in, const int* in_sizes, int n_in,
                              void* d_out, int out_size)
{
    const float* hs   = (const float*)d_in[0];
    const float* cosp = (const float*)d_in[1];
    const float* sinp = (const float*)d_in[2];
    const float* Wq   = (const float*)d_in[3];
    const float* bq   = (const float*)d_in[4];
    const float* Wk   = (const float*)d_in[5];
    const float* bk   = (const float*)d_in[6];
    const float* Wv   = (const float*)d_in[7];
    const float* bv   = (const float*)d_in[8];
    const float* Wp   = (const float*)d_in[9];
    const float* bp   = (const float*)d_in[10];
    float* out = (float*)d_out;

    float *pq, *pk, *pv;
    __nv_bfloat16 *pah, *pal, *pwh, *pwl;
    cudaGetSymbolAddress((void**)&pq,  g_q);
    cudaGetSymbolAddress((void**)&pk,  g_k);
    cudaGetSymbolAddress((void**)&pv,  g_v);
    cudaGetSymbolAddress((void**)&pah, g_ahi);
    cudaGetSymbolAddress((void**)&pal, g_alo);
    cudaGetSymbolAddress((void**)&pwh, g_whi);
    cudaGetSymbolAddress((void**)&pwl, g_wlo);

    PFN_tmap_encode enc = nullptr;
    cudaDriverEntryPointQueryResult qr;
    cudaGetDriverEntryPoint("cuTensorMapEncodeTiled", (void**)&enc,
                            cudaEnableDefault, &qr);
    CUtensorMap tmAh, tmAl, tmBh, tmBl;
    encode_map(enc, &tmAh, pah, SEQ);
    encode_map(enc, &tmAl, pal, SEQ);
    encode_map(enc, &tmBh, pwh, 3 * DIM);
    encode_map(enc, &tmBl, pwl, 3 * DIM);

    const int nA4 = SEQ * DIM / 4;
    const int nW4 = DIM * DIM / 4;

    cudaFuncSetAttribute(gemm_tc, cudaFuncAttributeMaxDynamicSharedMemorySize, SMEM_GEMM);

    split_kernel<<<(nA4 + 255) / 256, 256>>>(hs, pah, pal, nA4);
    split_kernel<<<(nW4 + 255) / 256, 256>>>(Wq, pwh,                 pwl,                 nW4);
    split_kernel<<<(nW4 + 255) / 256, 256>>>(Wk, pwh + DIM * DIM,     pwl + DIM * DIM,     nW4);
    split_kernel<<<(nW4 + 255) / 256, 256>>>(Wv, pwh + 2 * DIM * DIM, pwl + 2 * DIM * DIM, nW4);

    // fused QKV GEMM: grid (128, 15), cluster (2,1,1) pairs along M (x)
    gemm_tc<<<dim3(SEQ / TM, 3 * DIM / TN), 256, SMEM_GEMM>>>(
        tmAh, tmAl, tmBh, tmBl, pah, pal, pwh, pwl, pq, pk, pv, nullptr, 1);

    const int smem = (3 * WIN * HDP + WIN * SCP) * (int)sizeof(float);
    cudaFuncSetAttribute(attn_win, cudaFuncAttributeMaxDynamicSharedMemorySize, smem);
    attn_win<<<dim3(NWIN, NH), 256, smem>>>(cosp, sinp, bq, bk, bv);

    split_kernel<<<(nW4 + 255) / 256, 256>>>(Wp, pwh, pwl, nW4);
    // output projection with bias folded into epilogue
    gemm_tc<<<dim3(SEQ / TM, DIM / TN), 256, SMEM_GEMM>>>(
        tmAh, tmAl, tmBh, tmBl, pah, pal, pwh, pwl, out, out, out, bp, 0);
}

// round 10
// speedup vs baseline: 1.1808x; 1.0475x over previous
#include <cuda_runtime.h>
#include <cuda.h>
#include <cuda_bf16.h>
#include <mma.h>
#include <cstdint>

#define SEQ   16384
#define DIM   1280
#define NH    16
#define HD    80
#define WIN   64
#define NWIN  (SEQ / WIN)
#define HDP   84
#define SCP   65

// tcgen05 cg2 GEMM tiling: persistent pairs, 256x256 pair tile
#define TM    128          // M rows per CTA (pair tile M = 256)
#define TN    256          // N tile (each CTA holds N/2=128 B rows)
#define TKE   64           // K-chunk elements (128B SW128 row)
#define KSTG  (DIM / TKE)  // 20 k-stages per tile
#define NBUF  3
#define NPAIR 74           // persistent pairs (148 CTAs)
#define MT    64           // pair tiles along M (SEQ/256)

// smem layout (dynamic)
#define SM_TMEM   0
#define SM_FULL   8        // full[0..2] at 8,16,24 (leader)
#define SM_DONE   32       // done[0..2] at 32,40,48
#define SM_TILED  56       // tiledone[0..1] at 56,64
#define SM_BANKF  72       // bankfree[0..1] at 72,80
#define SM_BUF    1024
#define AB_QTR    16384                      // 128 rows x 128B
#define STAGE_BYTES (4 * AB_QTR)             // 64 KB per CTA per stage
#define SMEM_GEMM (SM_BUF + NBUF * STAGE_BYTES)
#define STAGE_TX  (2 * STAGE_BYTES)

#if defined(__CUDA_ARCH__) && (defined(__CUDA_ARCH_FEAT_SM103_ALL) || defined(__CUDA_ARCH_FEAT_SM100_ALL))
#define TC_PATH 1
#else
#define TC_PATH 0
#endif

// ---------------------------------------------------------------------------
__device__ float g_q[SEQ * DIM];
__device__ float g_k[SEQ * DIM];
__device__ float g_v[SEQ * DIM];
__device__ __nv_bfloat16 g_ahi[SEQ * DIM];
__device__ __nv_bfloat16 g_alo[SEQ * DIM];
__device__ __nv_bfloat16 g_whi[3 * DIM * DIM];
__device__ __nv_bfloat16 g_wlo[3 * DIM * DIM];

#if TC_PATH
__device__ __forceinline__ uint32_t smem_u32(const void* p) {
    uint32_t a;
    asm("{ .reg .u64 t; cvta.to.shared.u64 t, %1; cvt.u32.u64 %0, t; }"
        : "=r"(a) : "l"(p));
    return a;
}
__device__ __forceinline__ uint32_t ctarank() {
    uint32_t r;
    asm("mov.u32 %0, %%cluster_ctarank;" : "=r"(r));
    return r;
}
#define MBAR_INIT(addr, cnt) \
    asm volatile("mbarrier.init.shared.b64 [%0], %1;" :: "r"(addr), "r"(cnt) : "memory")
#define MBAR_EXPECT_TX(addr, tx) \
    asm volatile("mbarrier.arrive.expect_tx.shared.b64 _, [%0], %1;" :: "r"(addr), "r"(tx) : "memory")
// arrive on LEADER CTA's barrier (bit 24 cleared), cluster scope
#define MBAR_ARRIVE_LEADER(addr) \
    asm volatile("{ .reg .b32 la; and.b32 la, %0, 0xFEFFFFFF; " \
                 "mbarrier.arrive.shared::cluster.b64 _, [la]; }" :: "r"(addr) : "memory")

__device__ __forceinline__ void mbar_wait(uint32_t mbar, uint32_t phase) {
    asm volatile(
        "{\n\t.reg .pred P;\n\t"
        "WL_%=:\n\t"
        "mbarrier.try_wait.parity.acquire.cta.shared::cta.b64 P, [%0], %1, 0x989680;\n\t"
        "@P bra WD_%=;\n\t"
        "bra WL_%=;\n\t"
        "WD_%=:\n\t}"
        :: "r"(mbar), "r"(phase) : "memory");
}
#define CLUSTER_SYNC() do { \
    asm volatile("barrier.cluster.arrive.aligned;" ::: "memory"); \
    asm volatile("barrier.cluster.wait.aligned;" ::: "memory"); \
} while (0)

__device__ __forceinline__ void tma2d_cg2(uint32_t saddr, const void* tmap, int x, int y,
                                          uint32_t mbar) {
    asm volatile(
        "{\n\t.reg .b32 lb;\n\tand.b32 lb, %4, 0xFEFFFFFF;\n\t"
        "cp.async.bulk.tensor.2d.cta_group::2.shared::cluster.global.tile"
        ".mbarrier::complete_tx::bytes [%0], [%1, {%2, %3}], [lb];\n\t}"
        :: "r"(saddr), "l"(tmap), "r"(x), "r"(y), "r"(mbar) : "memory");
}
__device__ __forceinline__ uint64_t mk_desc(uint32_t addr) {
    return ((uint64_t)2 << 61) | ((uint64_t)1 << 46) | ((uint64_t)64 << 32) |
           ((uint64_t)1 << 16) | (uint64_t)((addr >> 4) & 0x3FFF);
}
__device__ __forceinline__ void mma_bf16_ss_cg2(uint32_t d, uint64_t ad, uint64_t bd,
                                                uint32_t idesc, uint32_t en) {
    asm volatile(
        "{\n\t.reg .pred p;\n\tsetp.ne.u32 p, %5, 0;\n\t"
        "tcgen05.mma.cta_group::2.kind::f16 [%0], %1, %2, %3, "
        "{%4, %4, %4, %4, %4, %4, %4, %4}, p;\n\t}"
        :: "r"(d), "l"(ad), "l"(bd), "r"(idesc), "r"(0u), "r"(en) : "memory");
}
#define TC_COMMIT_MC2(mbar, mask) \
    asm volatile("tcgen05.commit.cta_group::2.mbarrier::arrive::one.shared::cluster" \
                 ".multicast::cluster.b64 [%0], %1;" :: "r"(mbar), "h"((uint16_t)(mask)) : "memory")
#define TC_ALLOC2(slot, n) \
    asm volatile("tcgen05.alloc.cta_group::2.sync.aligned.shared::cta.b32 [%0], %1;" \
                 :: "r"(slot), "r"(n) : "memory")
#define TC_RELINQ2() \
    asm volatile("tcgen05.relinquish_alloc_permit.cta_group::2.sync.aligned;")
#define TC_DEALLOC2(t, n) \
    asm volatile("tcgen05.dealloc.cta_group::2.sync.aligned.b32 %0, %1;" :: "r"(t), "r"(n))
#define TC_FENCE_AFTER()  asm volatile("tcgen05.fence::after_thread_sync;" ::: "memory")
#define TC_FENCE_BEFORE() asm volatile("tcgen05.fence::before_thread_sync;" ::: "memory")
#define TC_WAIT_LD() asm volatile("tcgen05.wait::ld.sync.aligned;" ::: "memory")

#define LDTM_X32(r, addr) \
    asm volatile("tcgen05.ld.sync.aligned.32x32b.x32.b32 " \
        "{%0,%1,%2,%3,%4,%5,%6,%7,%8,%9,%10,%11,%12,%13,%14,%15," \
        "%16,%17,%18,%19,%20,%21,%22,%23,%24,%25,%26,%27,%28,%29,%30,%31}, [%32];" \
        : "=r"((r)[0]),"=r"((r)[1]),"=r"((r)[2]),"=r"((r)[3]), \
          "=r"((r)[4]),"=r"((r)[5]),"=r"((r)[6]),"=r"((r)[7]), \
          "=r"((r)[8]),"=r"((r)[9]),"=r"((r)[10]),"=r"((r)[11]), \
          "=r"((r)[12]),"=r"((r)[13]),"=r"((r)[14]),"=r"((r)[15]), \
          "=r"((r)[16]),"=r"((r)[17]),"=r"((r)[18]),"=r"((r)[19]), \
          "=r"((r)[20]),"=r"((r)[21]),"=r"((r)[22]),"=r"((r)[23]), \
          "=r"((r)[24]),"=r"((r)[25]),"=r"((r)[26]),"=r"((r)[27]), \
          "=r"((r)[28]),"=r"((r)[29]),"=r"((r)[30]),"=r"((r)[31]) \
        : "r"(addr))

// idesc: fp32 accum, bf16 a/b, N=256, M=256 (cg2 pair-wide)
#define IDESC2 ((1u << 4) | (1u << 7) | (1u << 10) | ((TN / 8) << 17) | (16u << 24))
#endif  // TC_PATH

// ---------------------------------------------------------------------------
__global__ void split_kernel(const float* __restrict__ src,
                             __nv_bfloat16* __restrict__ hi,
                             __nv_bfloat16* __restrict__ lo, int n4)
{
    int i = blockIdx.x * blockDim.x + threadIdx.x;
    if (i >= n4) return;
    float4 v = ((const float4*)src)[i];
    __nv_bfloat16 h0 = __float2bfloat16(v.x);
    __nv_bfloat16 h1 = __float2bfloat16(v.y);
    __nv_bfloat16 h2 = __float2bfloat16(v.z);
    __nv_bfloat16 h3 = __float2bfloat16(v.w);
    __nv_bfloat16 l0 = __float2bfloat16(v.x - __bfloat162float(h0));
    __nv_bfloat16 l1 = __float2bfloat16(v.y - __bfloat162float(h1));
    __nv_bfloat16 l2 = __float2bfloat16(v.z - __bfloat162float(h2));
    __nv_bfloat16 l3 = __float2bfloat16(v.w - __bfloat162float(h3));
    __nv_bfloat162* hp = (__nv_bfloat162*)hi;
    __nv_bfloat162* lp = (__nv_bfloat162*)lo;
    hp[2 * i]     = __nv_bfloat162(h0, h1);
    hp[2 * i + 1] = __nv_bfloat162(h2, h3);
    lp[2 * i]     = __nv_bfloat162(l0, l1);
    lp[2 * i + 1] = __nv_bfloat162(l2, l3);
}

// ---------------------------------------------------------------------------
// Persistent cg2 bf16x3 GEMM. 148 CTAs = 74 pairs; pair p handles tiles
// p, p+74, ... of ntiles. Tile t: pm = t%64 (M pair-tile), nidx = t/64.
// TMEM double-banked: tile i accumulates in bank i&1; epilogue of tile i
// overlaps MMAs of tile i+1. Warp 7 thread = TMA/MMA issuer; warps 0-3 =
// epilogue. fused=1 -> C in {cq,ck,cv} by nidx/5; else cq + bias.
// ---------------------------------------------------------------------------
__global__ __launch_bounds__(256, 1) __cluster_dims__(2, 1, 1)
void gemm_tc(const __grid_constant__ CUtensorMap tmAh,
             const __grid_constant__ CUtensorMap tmAl,
             const __grid_constant__ CUtensorMap tmBh,
             const __grid_constant__ CUtensorMap tmBl,
             const __nv_bfloat16* __restrict__ Ah,
             const __nv_bfloat16* __restrict__ Al,
             const __nv_bfloat16* __restrict__ Bh,
             const __nv_bfloat16* __restrict__ Bl,
             float* cq, float* ck, float* cv,
             const float* __restrict__ bias, int fused, int ntiles)
{
    extern __shared__ char smc[];
    const int tid = threadIdx.x;
    const int wid = tid >> 5;

#if TC_PATH
    const int lane = tid & 31;
    const uint32_t sbase = smem_u32(smc);
    const uint32_t rank = ctarank();
    const int p = blockIdx.x >> 1;                 // pair id
    const int myN = (ntiles - 1 - p) / NPAIR + 1;  // tiles for this pair
    const int total = myN * KSTG;

    if (tid == 0) {
#pragma unroll
        for (int s = 0; s < NBUF; s++) {
            MBAR_INIT(sbase + SM_FULL + 8 * s, 1);
            MBAR_INIT(sbase + SM_DONE + 8 * s, 1);
        }
        MBAR_INIT(sbase + SM_TILED, 1);
        MBAR_INIT(sbase + SM_TILED + 8, 1);
        MBAR_INIT(sbase + SM_BANKF, 2);      // one arrival per CTA
        MBAR_INIT(sbase + SM_BANKF + 8, 2);
    }
    if (wid == 0) {
        TC_ALLOC2(sbase + SM_TMEM, 512);
        TC_RELINQ2();
    }
    __syncthreads();
    CLUSTER_SYNC();

    uint32_t tmem;
    asm volatile("ld.shared.b32 %0, [%1];" : "=r"(tmem) : "r"(sbase + SM_TMEM));

    // ---------------- issuer: warp 7, one thread, both CTAs ----------------
    if (tid == 224) {
        auto issue = [&](int u, int b) {       // global stage u -> buffer b
            const int ti = u / KSTG, k = u - ti * KSTG;
            const int t = p + ti * NPAIR;
            const int pm = t & (MT - 1);
            const int nidx = t >> 6;
            const uint32_t buf = sbase + SM_BUF + b * STAGE_BYTES;
            const uint32_t fullb = sbase + SM_FULL + 8 * b;
            const int x = k * TKE;
            const int ay = pm * 256 + (int)rank * 128;
            const int by = nidx * 256 + (int)rank * 128;
            if (rank == 0) MBAR_EXPECT_TX(fullb, STAGE_TX);
            tma2d_cg2(buf,              &tmAh, x, ay, fullb);
            tma2d_cg2(buf + AB_QTR,     &tmAl, x, ay, fullb);
            tma2d_cg2(buf + 2 * AB_QTR, &tmBh, x, by, fullb);
            tma2d_cg2(buf + 3 * AB_QTR, &tmBl, x, by, fullb);
        };

        issue(0, 0);
        if (total > 1) issue(1, 1);
        if (total > 2) issue(2, 2);

        int pfull[NBUF] = {0, 0, 0}, pdone[NBUF] = {0, 0, 0}, pbank[2] = {0, 0};
        int ti = 0, k = 0;

        for (int s = 0; s < total; s++) {
            const int b = s % NBUF;

            if (rank == 0) {
                if (k == 0 && ti >= 2) {       // bank (ti&1) must be drained
                    const int bk = ti & 1;
                    mbar_wait(sbase + SM_BANKF + 8 * bk, pbank[bk]);
                    pbank[bk] ^= 1;
                }
                mbar_wait(sbase + SM_FULL + 8 * b, pfull[b]);
                pfull[b] ^= 1;

                const uint32_t dst = tmem + (uint32_t)((ti & 1) * 256);
                const uint32_t bufb = sbase + SM_BUF + b * STAGE_BYTES;
                uint64_t adh = mk_desc(bufb);
                uint64_t adl = mk_desc(bufb + AB_QTR);
                uint64_t bdh = mk_desc(bufb + 2 * AB_QTR);
                uint64_t bdl = mk_desc(bufb + 3 * AB_QTR);
#pragma unroll
                for (int ks = 0; ks < 4; ks++) {
                    mma_bf16_ss_cg2(dst, adh + 2 * ks, bdh + 2 * ks, IDESC2,
                                    (k == 0 && ks == 0) ? 0u : 1u);
                    mma_bf16_ss_cg2(dst, adh + 2 * ks, bdl + 2 * ks, IDESC2, 1u);
                    mma_bf16_ss_cg2(dst, adl + 2 * ks, bdh + 2 * ks, IDESC2, 1u);
                }
                TC_COMMIT_MC2(sbase + SM_DONE + 8 * b, 3);
                if (k == KSTG - 1)             // tile finished -> release epilogue
                    TC_COMMIT_MC2(sbase + SM_TILED + 8 * (ti & 1), 3);
            }

            // lagged refill: stage s-1's buffer gets stage s+2
            if (s >= 1 && s + 2 < total) {
                const int jb = (s - 1) % NBUF;
                mbar_wait(sbase + SM_DONE + 8 * jb, pdone[jb]);
                pdone[jb] ^= 1;
                issue(s + 2, jb);
            }

            if (++k == KSTG) { k = 0; ti++; }
        }
    }

    // ---------------- epilogue: warps 0-3, both CTAs ----------------
    if (wid < 4) {
        int ptile[2] = {0, 0};
        for (int i = 0; i < myN; i++) {
            const int t = p + i * NPAIR;
            const int pm = t & (MT - 1);
            const int nidx = t >> 6;
            float* C;
            int lcol;
            if (fused) {
                const int mtx = nidx / 5;
                C = (mtx == 0) ? cq : (mtx == 1) ? ck : cv;
                lcol = (nidx % 5) * TN;
            } else {
                C = cq;
                lcol = nidx * TN;
            }
            const int bk = i & 1;
            mbar_wait(sbase + SM_TILED + 8 * bk, ptile[bk]);
            ptile[bk] ^= 1;
            TC_FENCE_AFTER();

            const uint32_t tb = tmem + (uint32_t)(bk * 256);
            float* crow = C + (size_t)(pm * 256 + (int)rank * 128 + wid * 32 + lane) * DIM + lcol;
#pragma unroll
            for (int cc = 0; cc < 8; cc++) {
                uint32_t r[32];
                LDTM_X32(r, tb + cc * 32);
                TC_WAIT_LD();
                if (!fused) {
                    float4* cp = (float4*)(crow + cc * 32);
#pragma unroll
                    for (int q = 0; q < 8; q++) {
                        float4 bb = *(const float4*)(bias + lcol + cc * 32 + q * 4);
                        float4 v;
                        v.x = __uint_as_float(r[4 * q + 0]) + bb.x;
                        v.y = __uint_as_float(r[4 * q + 1]) + bb.y;
                        v.z = __uint_as_float(r[4 * q + 2]) + bb.z;
                        v.w = __uint_as_float(r[4 * q + 3]) + bb.w;
                        cp[q] = v;
                    }
                } else {
                    uint4* cp = (uint4*)(crow + cc * 32);
#pragma unroll
                    for (int q = 0; q < 8; q++)
                        cp[q] = make_uint4(r[4 * q], r[4 * q + 1], r[4 * q + 2], r[4 * q + 3]);
                }
            }
            TC_FENCE_BEFORE();
            asm volatile("bar.sync 1, 128;" ::: "memory");   // 4 epi warps of this CTA
            if (tid == 0)
                MBAR_ARRIVE_LEADER(sbase + SM_BANKF + 8 * bk);
        }
    }

    __syncthreads();
    if (wid == 0) TC_DEALLOC2(tmem, 512);
    CLUSTER_SYNC();

#else  // ------- wmma fallback (family/generic; correctness net) -------------
    using namespace nvcuda;
    const int GLDS = 40;
    __nv_bfloat16* sAh = (__nv_bfloat16*)smc;
    __nv_bfloat16* sAl = sAh + 128 * GLDS;
    __nv_bfloat16* sBh = sAl + 128 * GLDS;
    __nv_bfloat16* sBl = sBh + 128 * GLDS;

    const int wm = (wid & 1) * 64;
    const int wn = (wid >> 1) * 32;
    const int r0 = tid >> 2;
    const int c0 = (tid & 3) * 8;
    const int p = blockIdx.x >> 1;
    const int rk = blockIdx.x & 1;
    const int myN = (ntiles > p) ? ((ntiles - 1 - p) / NPAIR + 1) : 0;

    for (int it = 0; it < myN; it++) {
        const int t = p + it * NPAIR;
        const int pm = t & (MT - 1);
        const int nidx = t >> 6;
        float* C;
        int lcol;
        if (fused) {
            const int mtx = nidx / 5;
            C = (mtx == 0) ? cq : (mtx == 1) ? ck : cv;
            lcol = (nidx % 5) * TN;
        } else { C = cq; lcol = nidx * TN; }
        const int bm = pm * 256 + rk * 128;
        const int bng = nidx * TN;

        for (int half = 0; half < 2; half++) {
            const int bnh = bng + half * 128;
            wmma::fragment<wmma::accumulator, 16, 16, 16, float> acc[4][2];
#pragma unroll
            for (int i = 0; i < 4; i++)
#pragma unroll
                for (int j = 0; j < 2; j++) wmma::fill_fragment(acc[i][j], 0.0f);

            for (int k0 = 0; k0 < DIM; k0 += 32) {
                __syncthreads();
#pragma unroll
                for (int rr = 0; rr < 2; rr++) {
                    int row = r0 + rr * 64;
                    size_t ga = (size_t)(bm + row) * DIM + k0 + c0;
                    size_t gb = (size_t)(bnh + row) * DIM + k0 + c0;
                    *(uint4*)&sAh[row * GLDS + c0] = *(const uint4*)(Ah + ga);
                    *(uint4*)&sAl[row * GLDS + c0] = *(const uint4*)(Al + ga);
                    *(uint4*)&sBh[row * GLDS + c0] = *(const uint4*)(Bh + gb);
                    *(uint4*)&sBl[row * GLDS + c0] = *(const uint4*)(Bl + gb);
                }
                __syncthreads();
#pragma unroll
                for (int kk = 0; kk < 32; kk += 16) {
                    wmma::fragment<wmma::matrix_a, 16, 16, 16, __nv_bfloat16, wmma::row_major> fah[4], fal[4];
                    wmma::fragment<wmma::matrix_b, 16, 16, 16, __nv_bfloat16, wmma::col_major> fbh[2], fbl[2];
#pragma unroll
                    for (int i = 0; i < 4; i++) {
                        wmma::load_matrix_sync(fah[i], &sAh[(wm + i * 16) * GLDS + kk], GLDS);
                        wmma::load_matrix_sync(fal[i], &sAl[(wm + i * 16) * GLDS + kk], GLDS);
                    }
#pragma unroll
                    for (int j = 0; j < 2; j++) {
                        wmma::load_matrix_sync(fbh[j], &sBh[(wn + j * 16) * GLDS + kk], GLDS);
                        wmma::load_matrix_sync(fbl[j], &sBl[(wn + j * 16) * GLDS + kk], GLDS);
                    }
#pragma unroll
                    for (int i = 0; i < 4; i++)
#pragma unroll
                        for (int j = 0; j < 2; j++) {
                            wmma::mma_sync(acc[i][j], fah[i], fbh[j], acc[i][j]);
                            wmma::mma_sync(acc[i][j], fah[i], fbl[j], acc[i][j]);
                            wmma::mma_sync(acc[i][j], fal[i], fbh[j], acc[i][j]);
                        }
                }
            }
#pragma unroll
            for (int i = 0; i < 4; i++)
#pragma unroll
                for (int j = 0; j < 2; j++)
                    wmma::store_matrix_sync(&C[(size_t)(bm + wm + i * 16) * DIM + lcol + half * 128 + wn + j * 16],
                                            acc[i][j], DIM, wmma::mem_row_major);
            __syncthreads();
        }
        if (!fused && bias) {
            for (int idx = tid; idx < TM * TN; idx += 256) {
                int row = idx / TN, col = idx % TN;
                C[(size_t)(bm + row) * DIM + lcol + col] += bias[lcol + col];
            }
            __syncthreads();
        }
    }
#endif
}

// ---------------------------------------------------------------------------
// Windowed attention, fused bias + RoPE; 4x4 score / 4x5 PV register microtiles
// ---------------------------------------------------------------------------
__global__ __launch_bounds__(256)
void attn_win(const float* __restrict__ cosp, const float* __restrict__ sinp,
              const float* __restrict__ bq, const float* __restrict__ bk,
              const float* __restrict__ bv)
{
    extern __shared__ float sm[];
    float* qs = sm;
    float* ks = qs + WIN * HDP;
    float* vs = ks + WIN * HDP;
    float* sc = vs + WIN * HDP;

    const int w = blockIdx.x;
    const int h = blockIdx.y;
    const int tid = threadIdx.x;
    const size_t base = (size_t)(w * WIN) * DIM + (size_t)h * HD;

    for (int idx = tid; idx < WIN * (HD / 2); idx += 256) {
        int row = idx / (HD / 2);
        int d   = idx % (HD / 2);
        int s   = w * WIN + row;
        float c1 = cosp[s * HD + d],          s1 = sinp[s * HD + d];
        float c2 = cosp[s * HD + d + HD / 2], s2 = sinp[s * HD + d + HD / 2];
        size_t o1 = base + (size_t)row * DIM + d;
        size_t o2 = o1 + HD / 2;

        float q1 = g_q[o1] + bq[h * HD + d];
        float q2 = g_q[o2] + bq[h * HD + d + HD / 2];
        qs[row * HDP + d]          = q1 * c1 - q2 * s1;
        qs[row * HDP + d + HD / 2] = q2 * c2 + q1 * s2;

        float k1 = g_k[o1] + bk[h * HD + d];
        float k2 = g_k[o2] + bk[h * HD + d + HD / 2];
        ks[row * HDP + d]          = k1 * c1 - k2 * s1;
        ks[row * HDP + d + HD / 2] = k2 * c2 + k1 * s2;
    }
    for (int idx = tid; idx < WIN * (HD / 4); idx += 256) {
        int row = idx / (HD / 4);
        int col = (idx % (HD / 4)) * 4;
        size_t g = base + (size_t)row * DIM + col;
        float4 vv = *(const float4*)(g_v + g);
        vv.x += bv[h * HD + col + 0];
        vv.y += bv[h * HD + col + 1];
        vv.z += bv[h * HD + col + 2];
        vv.w += bv[h * HD + col + 3];
        *(float4*)(vs + row * HDP + col) = vv;
    }
    __syncthreads();

    const float scale = 0.11180339887498949f;
    {
        const int ti = (tid >> 4) * 4;
        const int tj = (tid & 15) * 4;
        float acc[4][4];
#pragma unroll
        for (int r = 0; r < 4; r++)
#pragma unroll
            for (int c = 0; c < 4; c++) acc[r][c] = 0.f;

        for (int d = 0; d < HD; d += 4) {
            float4 qv[4], kv[4];
#pragma unroll
            for (int r = 0; r < 4; r++) qv[r] = *(const float4*)(qs + (ti + r) * HDP + d);
#pragma unroll
            for (int c = 0; c < 4; c++) kv[c] = *(const float4*)(ks + (tj + c) * HDP + d);
#pragma unroll
            for (int r = 0; r < 4; r++)
#pragma unroll
                for (int c = 0; c < 4; c++)
                    acc[r][c] += qv[r].x * kv[c].x + qv[r].y * kv[c].y
                               + qv[r].z * kv[c].z + qv[r].w * kv[c].w;
        }
#pragma unroll
        for (int r = 0; r < 4; r++)
#pragma unroll
            for (int c = 0; c < 4; c++)
                sc[(ti + r) * SCP + tj + c] = acc[r][c] * scale;
    }
    __syncthreads();

    if (tid < WIN) {
        float m = -1e30f;
        for (int j = 0; j < WIN; j++) m = fmaxf(m, sc[tid * SCP + j]);
        float sum = 0.f;
        for (int j = 0; j < WIN; j++) {
            float e = __expf(sc[tid * SCP + j] - m);
            sc[tid * SCP + j] = e;
            sum += e;
        }
        float inv = 1.f / sum;
        for (int j = 0; j < WIN; j++) sc[tid * SCP + j] *= inv;
    }
    __syncthreads();

    {
        const int pr = (tid >> 4) * 4;
        const int pc = (tid & 15) * 5;
        float o[4][5];
#pragma unroll
        for (int r = 0; r < 4; r++)
#pragma unroll
            for (int c = 0; c < 5; c++) o[r][c] = 0.f;

        for (int j = 0; j < WIN; j++) {
            float sv[4], vv[5];
#pragma unroll
            for (int r = 0; r < 4; r++) sv[r] = sc[(pr + r) * SCP + j];
#pragma unroll
            for (int c = 0; c < 5; c++) vv[c] = vs[j * HDP + pc + c];
#pragma unroll
            for (int r = 0; r < 4; r++)
#pragma unroll
                for (int c = 0; c < 5; c++) o[r][c] += sv[r] * vv[c];
        }
#pragma unroll
        for (int r = 0; r < 4; r++) {
            size_t ob = base + (size_t)(pr + r) * DIM + pc;
#pragma unroll
            for (int c = 0; c < 5; c++) {
                __nv_bfloat16 hi = __float2bfloat16(o[r][c]);
                g_ahi[ob + c] = hi;
                g_alo[ob + c] = __float2bfloat16(o[r][c] - __bfloat162float(hi));
            }
        }
    }
}

// ---------------------------------------------------------------------------
typedef CUresult (*PFN_tmap_encode)(
    CUtensorMap*, CUtensorMapDataType, cuuint32_t, void*,
    const cuuint64_t*, const cuuint64_t*, const cuuint32_t*, const cuuint32_t*,
    CUtensorMapInterleave, CUtensorMapSwizzle, CUtensorMapL2promotion,
    CUtensorMapFloatOOBfill);

static void encode_map(PFN_tmap_encode enc, CUtensorMap* m, void* base, uint64_t rows)
{
    cuuint64_t dims[2]    = {DIM, rows};
    cuuint64_t strides[1] = {DIM * 2};
    cuuint32_t box[2]     = {64, 128};
    cuuint32_t es[2]      = {1, 1};
    enc(m, CU_TENSOR_MAP_DATA_TYPE_BFLOAT16, 2, base, dims, strides, box, es,
        CU_TENSOR_MAP_INTERLEAVE_NONE, CU_TENSOR_MAP_SWIZZLE_128B,
        CU_TENSOR_MAP_L2_PROMOTION_L2_128B, CU_TENSOR_MAP_FLOAT_OOB_FILL_NONE);
}

extern "C" void kernel_launch(void* const* d_in, const int* in_sizes, int n_in,
                              void* d_out, int out_size)
{
    const float* hs   = (const float*)d_in[0];
    const float* cosp = (const float*)d_in[1];
    const float* sinp = (const float*)d_in[2];
    const float* Wq   = (const float*)d_in[3];
    const float* bq   = (const float*)d_in[4];
    const float* Wk   = (const float*)d_in[5];
    const float* bk   = (const float*)d_in[6];
    const float* Wv   = (const float*)d_in[7];
    const float* bv   = (const float*)d_in[8];
    const float* Wp   = (const float*)d_in[9];
    const float* bp   = (const float*)d_in[10];
    float* out = (float*)d_out;

    float *pq, *pk, *pv;
    __nv_bfloat16 *pah, *pal, *pwh, *pwl;
    cudaGetSymbolAddress((void**)&pq,  g_q);
    cudaGetSymbolAddress((void**)&pk,  g_k);
    cudaGetSymbolAddress((void**)&pv,  g_v);
    cudaGetSymbolAddress((void**)&pah, g_ahi);
    cudaGetSymbolAddress((void**)&pal, g_alo);
    cudaGetSymbolAddress((void**)&pwh, g_whi);
    cudaGetSymbolAddress((void**)&pwl, g_wlo);

    PFN_tmap_encode enc = nullptr;
    cudaDriverEntryPointQueryResult qr;
    cudaGetDriverEntryPoint("cuTensorMapEncodeTiled", (void**)&enc,
                            cudaEnableDefault, &qr);
    CUtensorMap tmAh, tmAl, tmBh, tmBl;
    encode_map(enc, &tmAh, pah, SEQ);
    encode_map(enc, &tmAl, pal, SEQ);
    encode_map(enc, &tmBh, pwh, 3 * DIM);
    encode_map(enc, &tmBl, pwl, 3 * DIM);

    const int nA4 = SEQ * DIM / 4;
    const int nW4 = DIM * DIM / 4;

    cudaFuncSetAttribute(gemm_tc, cudaFuncAttributeMaxDynamicSharedMemorySize, SMEM_GEMM);

    split_kernel<<<(nA4 + 255) / 256, 256>>>(hs, pah, pal, nA4);
    split_kernel<<<(nW4 + 255) / 256, 256>>>(Wq, pwh,                 pwl,                 nW4);
    split_kernel<<<(nW4 + 255) / 256, 256>>>(Wk, pwh + DIM * DIM,     pwl + DIM * DIM,     nW4);
    split_kernel<<<(nW4 + 255) / 256, 256>>>(Wv, pwh + 2 * DIM * DIM, pwl + 2 * DIM * DIM, nW4);

    // fused QKV: 960 pair-tiles over 74 persistent pairs
    gemm_tc<<<dim3(2 * NPAIR, 1), 256, SMEM_GEMM>>>(
        tmAh, tmAl, tmBh, tmBl, pah, pal, pwh, pwl, pq, pk, pv, nullptr, 1,
        MT * (3 * DIM / TN));

    const int smem = (3 * WIN * HDP + WIN * SCP) * (int)sizeof(float);
    cudaFuncSetAttribute(attn_win, cudaFuncAttributeMaxDynamicSharedMemorySize, smem);
    attn_win<<<dim3(NWIN, NH), 256, smem>>>(cosp, sinp, bq, bk, bv);

    split_kernel<<<(nW4 + 255) / 256, 256>>>(Wp, pwh, pwl, nW4);
    // output projection: 320 pair-tiles, bias folded
    gemm_tc<<<dim3(2 * NPAIR, 1), 256, SMEM_GEMM>>>(
        tmAh, tmAl, tmBh, tmBl, pah, pal, pwh, pwl, out, out, out, bp, 0,
        MT * (DIM / TN));
}